// round 15
// baseline (speedup 1.0000x reference)
#include <cuda_runtime.h>
#include <cuda_bf16.h>
#include <mma.h>
#include <cstdint>
#include <math.h>

using namespace nvcuda;

// ---------------------------------------------------------------------------
// Problem constants
// ---------------------------------------------------------------------------
#define BATCH   16384
#define SEQ     8
#define MTOK    (BATCH * SEQ)     // 131072 token rows
#define MSEL    BATCH             // 16384 selected rows (layer 2 compact path)
#define DM      512
#define DH      2048
#define DQKV    1536              // fused q|k|v width (layer 1)
#define LN_EPS  1e-6f

// GEMM tiling: BM=128, BN=256, BK=32; 8 warps as 2(M)x4(N); warp tile 64x64.
#define BM      128
#define BN      256
#define BK      32
#define SSTRIDE 40                               // smem row stride in bf16 (80B)
#define APLANE  10240u                           // 128 rows * 80B
#define BPLANE  20480u                           // 256 rows * 80B
#define STAGE_BYTES (2u * APLANE + 2u * BPLANE)  // 61440: Ahi|Alo|Bhi|Blo
#define CSTRIDE 264                              // epilogue fp32 stride (1056B)
#define GSMEM   (128u * CSTRIDE * 4u)            // 135168 >= 2*STAGE_BYTES=122880

// ---------------------------------------------------------------------------
// Scratch (device globals = legal scratch)
// ---------------------------------------------------------------------------
__device__ __nv_bfloat16 g_h_hi  [(size_t)MTOK * DM];
__device__ __nv_bfloat16 g_h_lo  [(size_t)MTOK * DM];
__device__ __nv_bfloat16 g_qkv_hi[(size_t)MTOK * DQKV];   // L1: qkv. L2: kv [M][1024]
__device__ __nv_bfloat16 g_qkv_lo[(size_t)MTOK * DQKV];
__device__ __nv_bfloat16 g_ctx_hi[(size_t)MTOK * DM];
__device__ __nv_bfloat16 g_ctx_lo[(size_t)MTOK * DM];
__device__ __nv_bfloat16 g_t_hi  [(size_t)MTOK * DM];
__device__ __nv_bfloat16 g_t_lo  [(size_t)MTOK * DM];
__device__ __nv_bfloat16 g_mid_hi[(size_t)MTOK * DH];
__device__ __nv_bfloat16 g_mid_lo[(size_t)MTOK * DH];
// layer-2 compact buffers
__device__ __nv_bfloat16 g_sh_hi [(size_t)MSEL * DM];
__device__ __nv_bfloat16 g_sh_lo [(size_t)MSEL * DM];
__device__ __nv_bfloat16 g_qs_hi [(size_t)MSEL * DM];
__device__ __nv_bfloat16 g_qs_lo [(size_t)MSEL * DM];
// split-transposed weights, both layers resident
__device__ __nv_bfloat16 g_wqkvT_hi[2][(size_t)DQKV * DM];
__device__ __nv_bfloat16 g_wqkvT_lo[2][(size_t)DQKV * DM];
__device__ __nv_bfloat16 g_woT_hi  [2][(size_t)DM * DM];
__device__ __nv_bfloat16 g_woT_lo  [2][(size_t)DM * DM];
__device__ __nv_bfloat16 g_w1T_hi  [2][(size_t)DH * DM];
__device__ __nv_bfloat16 g_w1T_lo  [2][(size_t)DH * DM];
__device__ __nv_bfloat16 g_w2T_hi  [2][(size_t)DM * DH];
__device__ __nv_bfloat16 g_w2T_lo  [2][(size_t)DM * DH];
__device__ float         g_bqkv   [2][DQKV];

// ---------------------------------------------------------------------------
// Helpers
// ---------------------------------------------------------------------------
__device__ __forceinline__ uint32_t smem_u32(const void* p) {
    uint32_t a;
    asm("{ .reg .u64 t; cvta.to.shared.u64 t, %1; cvt.u32.u64 %0, t; }" : "=r"(a) : "l"(p));
    return a;
}
__device__ __forceinline__ void cp16(uint32_t sm, const void* g) {
    asm volatile("cp.async.cg.shared.global [%0], [%1], 16;" :: "r"(sm), "l"(g));
}
__device__ __forceinline__ void split2(float x, __nv_bfloat16& hi, __nv_bfloat16& lo) {
    hi = __float2bfloat16(x);
    lo = __float2bfloat16(x - __bfloat162float(hi));
}
__device__ __forceinline__ float join2(__nv_bfloat16 hi, __nv_bfloat16 lo) {
    return __bfloat162float(hi) + __bfloat162float(lo);
}
__device__ __forceinline__ float joinu(uint32_t h, uint32_t l) {
    return __bfloat162float(__ushort_as_bfloat16((unsigned short)h)) +
           __bfloat162float(__ushort_as_bfloat16((unsigned short)l));
}
__device__ __forceinline__ unsigned packbf(__nv_bfloat16 a, __nv_bfloat16 b) {
    return (unsigned)__bfloat16_as_ushort(a) | ((unsigned)__bfloat16_as_ushort(b) << 16);
}

// ---------------------------------------------------------------------------
// wmma GEMM: C[M,N] = A @ B^T + bias (+relu), hi/lo planes, 3-product comp.
// 64x64 warp tile (2x4 warp grid, BN=256); 1 CTA/SM, full 255-reg budget.
// ---------------------------------------------------------------------------
__global__ __launch_bounds__(256)
void gemm_wmma(const __nv_bfloat16* __restrict__ Ahi, const __nv_bfloat16* __restrict__ Alo,
               const __nv_bfloat16* __restrict__ Bhi, const __nv_bfloat16* __restrict__ Blo,
               const float* __restrict__ bias,
               __nv_bfloat16* __restrict__ Chi, __nv_bfloat16* __restrict__ Clo,
               int N, int K, int relu)
{
    extern __shared__ char smem[];
    const uint32_t sb = smem_u32(smem);
    const int tid = threadIdx.x;
    const int wid = tid >> 5;
    const int wy  = wid & 1;          // 2 warps along M (64 rows each)
    const int wx  = wid >> 1;         // 4 warps along N (64 cols each)
    const int m0  = blockIdx.y << 7;  // BM=128
    const int n0  = blockIdx.x << 8;  // BN=256
    const int NC  = K / BK;

    wmma::fragment<wmma::accumulator, 16, 16, 16, float> acc[4][4];
#pragma unroll
    for (int m = 0; m < 4; m++)
#pragma unroll
        for (int n = 0; n < 4; n++) wmma::fill_fragment(acc[m][n], 0.0f);

    // stage loader: Ahi|Alo 128 rows, Bhi|Blo 256 rows; 64B/row as 4x16B.
    // 3072 chunks total, 12 per thread.
    auto load_stage = [&](int st, int k0) {
        const uint32_t base = sb + (uint32_t)st * STAGE_BYTES;
#pragma unroll
        for (int it = 0; it < 12; it++) {
            const int i = tid + it * 256;
            int r;
            uint32_t pbase;
            const __nv_bfloat16* gp;
            if (i < 512) {
                r = i >> 2;          pbase = 0u;
                gp = Ahi + (size_t)(m0 + r) * K + k0;
            } else if (i < 1024) {
                r = (i - 512) >> 2;  pbase = APLANE;
                gp = Alo + (size_t)(m0 + r) * K + k0;
            } else if (i < 2048) {
                r = (i - 1024) >> 2; pbase = 2u * APLANE;
                gp = Bhi + (size_t)(n0 + r) * K + k0;
            } else {
                r = (i - 2048) >> 2; pbase = 2u * APLANE + BPLANE;
                gp = Blo + (size_t)(n0 + r) * K + k0;
            }
            const int c = (i & 3) << 4;
            cp16(base + pbase + (uint32_t)r * (SSTRIDE * 2) + c, (const char*)gp + c);
        }
        asm volatile("cp.async.commit_group;" ::: "memory");
    };

    load_stage(0, 0);

    for (int ch = 0; ch < NC; ch++) {
        if (ch + 1 < NC) {
            load_stage((ch + 1) & 1, (ch + 1) * BK);
            asm volatile("cp.async.wait_group 1;" ::: "memory");
        } else {
            asm volatile("cp.async.wait_group 0;" ::: "memory");
        }
        __syncthreads();

        const __nv_bfloat16* ss =
            (const __nv_bfloat16*)(smem + (size_t)(ch & 1) * STAGE_BYTES);
        const __nv_bfloat16* sAhi = ss;
        const __nv_bfloat16* sAlo = ss + 128 * SSTRIDE;
        const __nv_bfloat16* sBhi = ss + 2 * 128 * SSTRIDE;
        const __nv_bfloat16* sBlo = ss + 2 * 128 * SSTRIDE + 256 * SSTRIDE;

#pragma unroll
        for (int ks = 0; ks < 2; ks++) {
            wmma::fragment<wmma::matrix_a, 16, 16, 16, __nv_bfloat16, wmma::row_major> ah[4], al[4];
#pragma unroll
            for (int m = 0; m < 4; m++) {
                const int row = wy * 64 + m * 16;
                wmma::load_matrix_sync(ah[m], sAhi + row * SSTRIDE + ks * 16, SSTRIDE);
                wmma::load_matrix_sync(al[m], sAlo + row * SSTRIDE + ks * 16, SSTRIDE);
            }
#pragma unroll
            for (int n = 0; n < 4; n++) {
                const int col = wx * 64 + n * 16;
                wmma::fragment<wmma::matrix_b, 16, 16, 16, __nv_bfloat16, wmma::col_major> bh, bl;
                wmma::load_matrix_sync(bh, sBhi + col * SSTRIDE + ks * 16, SSTRIDE);
                wmma::load_matrix_sync(bl, sBlo + col * SSTRIDE + ks * 16, SSTRIDE);
#pragma unroll
                for (int m = 0; m < 4; m++) {
                    wmma::mma_sync(acc[m][n], ah[m], bh, acc[m][n]);
                    wmma::mma_sync(acc[m][n], ah[m], bl, acc[m][n]);
                    wmma::mma_sync(acc[m][n], al[m], bh, acc[m][n]);
                }
            }
        }
        __syncthreads();
    }

    // ---- epilogue: stage acc -> smem fp32 (128 x 256, stride 264) ----
    float* cs = (float*)smem;
#pragma unroll
    for (int m = 0; m < 4; m++)
#pragma unroll
        for (int n = 0; n < 4; n++)
            wmma::store_matrix_sync(cs + (size_t)(wy * 64 + m * 16) * CSTRIDE
                                       + wx * 64 + n * 16,
                                    acc[m][n], CSTRIDE, wmma::mem_row_major);
    __syncthreads();

    {
        const int r    = tid >> 1;             // 0..127
        const int half = tid & 1;              // 2 halves of 128 cols
        const int row  = m0 + r;
        const int cb   = half * 128;
        const float* src = cs + (size_t)r * CSTRIDE + cb;
        __nv_bfloat16* dh = Chi + (size_t)row * N + n0 + cb;
        __nv_bfloat16* dl = Clo + (size_t)row * N + n0 + cb;
        const float* bp = bias + n0 + cb;
#pragma unroll
        for (int g = 0; g < 16; g++) {
            unsigned hw[4], lw[4];
#pragma unroll
            for (int j = 0; j < 4; j++) {
                float v0 = src[g * 8 + 2 * j]     + bp[g * 8 + 2 * j];
                float v1 = src[g * 8 + 2 * j + 1] + bp[g * 8 + 2 * j + 1];
                if (relu) { v0 = fmaxf(v0, 0.0f); v1 = fmaxf(v1, 0.0f); }
                __nv_bfloat16 h0, l0, h1, l1;
                split2(v0, h0, l0);
                split2(v1, h1, l1);
                hw[j] = packbf(h0, h1);
                lw[j] = packbf(l0, l1);
            }
            *(uint4*)(dh + g * 8) = *(const uint4*)hw;
            *(uint4*)(dl + g * 8) = *(const uint4*)lw;
        }
    }
}

// ---------------------------------------------------------------------------
// Fused weight prep for one layer (6 matrices, one launch of 3072 blocks)
// ---------------------------------------------------------------------------
__global__ __launch_bounds__(256)
void wprep_kernel(const float* __restrict__ Wq, const float* __restrict__ Wk,
                  const float* __restrict__ Wv, const float* __restrict__ Wo,
                  const float* __restrict__ W1, const float* __restrict__ W2,
                  __nv_bfloat16* __restrict__ qkvThi, __nv_bfloat16* __restrict__ qkvTlo,
                  __nv_bfloat16* __restrict__ woThi,  __nv_bfloat16* __restrict__ woTlo,
                  __nv_bfloat16* __restrict__ w1Thi,  __nv_bfloat16* __restrict__ w1Tlo,
                  __nv_bfloat16* __restrict__ w2Thi,  __nv_bfloat16* __restrict__ w2Tlo)
{
    __shared__ float tile[32][33];
    const int t = blockIdx.x;
    const float* W;
    int K, N, rowOff, bx, by;
    __nv_bfloat16 *Thi, *Tlo;

    if (t < 768) {                    // Wq|Wk|Wv -> fused qkvT
        const int g = t >> 8, r = t & 255;
        W = (g == 0) ? Wq : (g == 1) ? Wk : Wv;
        K = DM; N = DM; rowOff = g * DM;
        bx = r & 15; by = r >> 4;
        Thi = qkvThi; Tlo = qkvTlo;
    } else if (t < 1024) {            // Wo
        const int r = t - 768;
        W = Wo; K = DM; N = DM; rowOff = 0;
        bx = r & 15; by = r >> 4;
        Thi = woThi; Tlo = woTlo;
    } else if (t < 2048) {            // W1: [512,2048]
        const int r = t - 1024;
        W = W1; K = DM; N = DH; rowOff = 0;
        bx = r & 63; by = r >> 6;
        Thi = w1Thi; Tlo = w1Tlo;
    } else {                          // W2: [2048,512]
        const int r = t - 2048;
        W = W2; K = DH; N = DM; rowOff = 0;
        bx = r & 15; by = r >> 4;
        Thi = w2Thi; Tlo = w2Tlo;
    }

    const int tx = threadIdx.x & 31, ty = threadIdx.x >> 5;
    const int n0 = bx << 5, k0 = by << 5;
#pragma unroll
    for (int r = 0; r < 4; r++) {
        int k = k0 + ty + r * 8;
        tile[ty + r * 8][tx] = W[(size_t)k * N + n0 + tx];
    }
    __syncthreads();
#pragma unroll
    for (int r = 0; r < 4; r++) {
        int n = n0 + ty + r * 8;
        float v = tile[tx][ty + r * 8];
        __nv_bfloat16 hi, lo;
        split2(v, hi, lo);
        size_t o = (size_t)(rowOff + n) * K + k0 + tx;
        Thi[o] = hi;
        Tlo[o] = lo;
    }
}

__global__ void bcat_kernel(const float* __restrict__ a, const float* __restrict__ b,
                            const float* __restrict__ c, float* __restrict__ o) {
    int t = blockIdx.x * 256 + threadIdx.x;
    if (t < 512) o[t] = a[t];
    else if (t < 1024) o[t] = b[t - 512];
    else if (t < 1536) o[t] = c[t - 1024];
}

// ---------------------------------------------------------------------------
// Positional encoding: h = split(x + sinusoid)
// ---------------------------------------------------------------------------
__global__ void pos_kernel(const float* __restrict__ x,
                           __nv_bfloat16* __restrict__ hhi, __nv_bfloat16* __restrict__ hlo) {
    int t = blockIdx.x * 256 + threadIdx.x;
    int c = t & 511;
    int s = (t >> 9) & 7;
    int d2 = c >> 1;
    float e = (float)(2 * d2) * (1.0f / 512.0f);
    float ang = (float)s * powf(10000.0f, -e);
    float p = (c & 1) ? cosf(ang) : sinf(ang);
    __nv_bfloat16 hi, lo;
    split2(x[t] + p, hi, lo);
    hhi[t] = hi;
    hlo[t] = lo;
}

// ---------------------------------------------------------------------------
// Layer-1 attention: qkv fused planes [M][1536] -> ctx planes [M][512]
// ---------------------------------------------------------------------------
__global__ __launch_bounds__(256)
void attn_kernel(const __nv_bfloat16* __restrict__ qh, const __nv_bfloat16* __restrict__ ql,
                 __nv_bfloat16* __restrict__ ch, __nv_bfloat16* __restrict__ cl) {
    __shared__ float qs[8][512];
    __shared__ float ks[8][512];
    __shared__ float sc[8][8][8];

    const int b = blockIdx.x, tid = threadIdx.x;
    const size_t rbase = (size_t)b * 8 * DQKV;

    for (int t = tid; t < 512; t += 256) {
        int i = t >> 6;
        int c8 = (t & 63) << 3;
        size_t qo = rbase + (size_t)i * DQKV + c8;
        uint4 h4 = *(const uint4*)(qh + qo);
        uint4 l4 = *(const uint4*)(ql + qo);
        const unsigned* hu = (const unsigned*)&h4;
        const unsigned* lu = (const unsigned*)&l4;
#pragma unroll
        for (int w = 0; w < 4; w++) {
            qs[i][c8 + 2 * w]     = joinu(hu[w] & 0xFFFFu, lu[w] & 0xFFFFu);
            qs[i][c8 + 2 * w + 1] = joinu(hu[w] >> 16,     lu[w] >> 16);
        }
        size_t ko = qo + 512;
        h4 = *(const uint4*)(qh + ko);
        l4 = *(const uint4*)(ql + ko);
#pragma unroll
        for (int w = 0; w < 4; w++) {
            ks[i][c8 + 2 * w]     = joinu(hu[w] & 0xFFFFu, lu[w] & 0xFFFFu);
            ks[i][c8 + 2 * w + 1] = joinu(hu[w] >> 16,     lu[w] >> 16);
        }
    }
    __syncthreads();

    for (int t = tid; t < 512; t += 256) {
        int h = t >> 6, r = t & 63, i = r >> 3, j = r & 7;
        const float* qp = &qs[i][h * 64];
        const float* kp = &ks[j][h * 64];
        float s = 0.0f;
#pragma unroll
        for (int d = 0; d < 64; d++) s = fmaf(qp[d], kp[d], s);
        sc[h][i][j] = s * 0.125f;
    }
    __syncthreads();

    if (tid < 64) {
        int h = tid >> 3, i = tid & 7;
        float* row = sc[h][i];
        float m = row[0];
#pragma unroll
        for (int j = 1; j < 8; j++) m = fmaxf(m, row[j]);
        float e[8], s = 0.0f;
#pragma unroll
        for (int j = 0; j < 8; j++) { e[j] = expf(row[j] - m); s += e[j]; }
        float inv = 1.0f / s;
#pragma unroll
        for (int j = 0; j < 8; j++) row[j] = e[j] * inv;
    }
    __syncthreads();

    const size_t obase = (size_t)b * 8 * DM;
    for (int t = tid; t < 4096; t += 256) {
        int i = t >> 9, c = t & 511, h = c >> 6;
        const __nv_bfloat16* vh = qh + rbase + 1024 + c;
        const __nv_bfloat16* vl = ql + rbase + 1024 + c;
        const float* ar = sc[h][i];
        float s = 0.0f;
#pragma unroll
        for (int j = 0; j < 8; j++) {
            float vv = join2(vh[(size_t)j * DQKV], vl[(size_t)j * DQKV]);
            s = fmaf(ar[j], vv, s);
        }
        __nv_bfloat16 hi, lo;
        split2(s, hi, lo);
        size_t o = obase + (size_t)i * DM + c;
        ch[o] = hi;
        cl[o] = lo;
    }
}

// ---------------------------------------------------------------------------
// Layer-2 selected-query attention: qsel [B][512], kv [M][1024] -> ctx [B][512]
// ---------------------------------------------------------------------------
__global__ __launch_bounds__(256)
void attn_sel_kernel(const __nv_bfloat16* __restrict__ qh, const __nv_bfloat16* __restrict__ ql,
                     const __nv_bfloat16* __restrict__ kvh, const __nv_bfloat16* __restrict__ kvl,
                     __nv_bfloat16* __restrict__ ch, __nv_bfloat16* __restrict__ cl) {
    __shared__ float qs[512];
    __shared__ float ks[8][512];
    __shared__ float sc[8][8];          // [head][key]

    const int b = blockIdx.x, tid = threadIdx.x;
    const size_t qbase  = (size_t)b * DM;
    const size_t kvbase = (size_t)b * 8 * 1024;

    for (int t = tid; t < 512; t += 256)
        qs[t] = join2(qh[qbase + t], ql[qbase + t]);
    for (int t = tid; t < 4096; t += 256) {
        int j = t >> 9, c = t & 511;
        size_t o = kvbase + (size_t)j * 1024 + c;
        ks[j][c] = join2(kvh[o], kvl[o]);
    }
    __syncthreads();

    if (tid < 64) {
        int h = tid >> 3, j = tid & 7;
        const float* qp = &qs[h * 64];
        const float* kp = &ks[j][h * 64];
        float s = 0.0f;
#pragma unroll
        for (int d = 0; d < 64; d++) s = fmaf(qp[d], kp[d], s);
        sc[h][j] = s * 0.125f;
    }
    __syncthreads();

    if (tid < 8) {
        float* row = sc[tid];
        float m = row[0];
#pragma unroll
        for (int j = 1; j < 8; j++) m = fmaxf(m, row[j]);
        float e[8], s = 0.0f;
#pragma unroll
        for (int j = 0; j < 8; j++) { e[j] = expf(row[j] - m); s += e[j]; }
        float inv = 1.0f / s;
#pragma unroll
        for (int j = 0; j < 8; j++) row[j] = e[j] * inv;
    }
    __syncthreads();

    for (int t = tid; t < 512; t += 256) {
        int h = t >> 6;
        const float* ar = sc[h];
        float s = 0.0f;
#pragma unroll
        for (int j = 0; j < 8; j++) {
            size_t o = kvbase + (size_t)j * 1024 + 512 + t;
            s = fmaf(ar[j], join2(kvh[o], kvl[o]), s);
        }
        __nv_bfloat16 hi, lo;
        split2(s, hi, lo);
        ch[qbase + t] = hi;
        cl[qbase + t] = lo;
    }
}

// ---------------------------------------------------------------------------
// Row gather: sel[b][:] = h[b*8 + b%8][:]
// ---------------------------------------------------------------------------
__global__ void selgather_kernel(const __nv_bfloat16* __restrict__ hh,
                                 const __nv_bfloat16* __restrict__ hl,
                                 __nv_bfloat16* __restrict__ sh,
                                 __nv_bfloat16* __restrict__ sl) {
    int t = blockIdx.x * 256 + threadIdx.x;      // < MSEL*DM
    int b = t >> 9, c = t & 511;
    size_t src = ((size_t)b * 8 + (b & 7)) * DM + c;
    sh[t] = hh[src];
    sl[t] = hl[src];
}

// ---------------------------------------------------------------------------
// Residual + LayerNorm -> split planes (in-place on h)
// ---------------------------------------------------------------------------
__global__ __launch_bounds__(128)
void ln_kernel(const __nv_bfloat16* __restrict__ th, const __nv_bfloat16* __restrict__ tl,
               __nv_bfloat16* __restrict__ hh, __nv_bfloat16* __restrict__ hl,
               const float* __restrict__ g, const float* __restrict__ bb) {
    const int row = blockIdx.x, tid = threadIdx.x;
    const size_t base = (size_t)row * DM + tid * 4;

    float x[4];
#pragma unroll
    for (int j = 0; j < 4; j++)
        x[j] = join2(th[base + j], tl[base + j]) + join2(hh[base + j], hl[base + j]);

    float s = x[0] + x[1] + x[2] + x[3];
#pragma unroll
    for (int o = 16; o; o >>= 1) s += __shfl_xor_sync(0xFFFFFFFFu, s, o);

    __shared__ float sm1[4], sm2[4];
    const int w = tid >> 5, lane = tid & 31;
    if (!lane) sm1[w] = s;
    __syncthreads();
    float mu = (sm1[0] + sm1[1] + sm1[2] + sm1[3]) * (1.0f / 512.0f);

    float d0 = x[0] - mu, d1 = x[1] - mu, d2 = x[2] - mu, d3 = x[3] - mu;
    float ss = d0 * d0 + d1 * d1 + d2 * d2 + d3 * d3;
#pragma unroll
    for (int o = 16; o; o >>= 1) ss += __shfl_xor_sync(0xFFFFFFFFu, ss, o);
    if (!lane) sm2[w] = ss;
    __syncthreads();
    float var = (sm2[0] + sm2[1] + sm2[2] + sm2[3]) * (1.0f / 512.0f);
    float inv = rsqrtf(var + LN_EPS);

    float4 gg = ((const float4*)g)[tid];
    float4 bv = ((const float4*)bb)[tid];
    float o0 = d0 * inv * gg.x + bv.x;
    float o1 = d1 * inv * gg.y + bv.y;
    float o2 = d2 * inv * gg.z + bv.z;
    float o3 = d3 * inv * gg.w + bv.w;

    __nv_bfloat16 a0, b0, a1, b1, a2, b2, a3, b3;
    split2(o0, a0, b0);
    split2(o1, a1, b1);
    split2(o2, a2, b2);
    split2(o3, a3, b3);
    uint2 oh = make_uint2(packbf(a0, a1), packbf(a2, a3));
    uint2 ol = make_uint2(packbf(b0, b1), packbf(b2, b3));
    *(uint2*)(hh + base) = oh;
    *(uint2*)(hl + base) = ol;
}

// ---------------------------------------------------------------------------
// Final residual + LayerNorm -> fp32 output
// ---------------------------------------------------------------------------
__global__ __launch_bounds__(128)
void lnout_kernel(const __nv_bfloat16* __restrict__ th, const __nv_bfloat16* __restrict__ tl,
                  const __nv_bfloat16* __restrict__ hh, const __nv_bfloat16* __restrict__ hl,
                  const float* __restrict__ g, const float* __restrict__ bb,
                  float* __restrict__ out) {
    const int row = blockIdx.x, tid = threadIdx.x;
    const size_t base = (size_t)row * DM + tid * 4;

    float x[4];
#pragma unroll
    for (int j = 0; j < 4; j++)
        x[j] = join2(th[base + j], tl[base + j]) + join2(hh[base + j], hl[base + j]);

    float s = x[0] + x[1] + x[2] + x[3];
#pragma unroll
    for (int o = 16; o; o >>= 1) s += __shfl_xor_sync(0xFFFFFFFFu, s, o);

    __shared__ float sm1[4], sm2[4];
    const int w = tid >> 5, lane = tid & 31;
    if (!lane) sm1[w] = s;
    __syncthreads();
    float mu = (sm1[0] + sm1[1] + sm1[2] + sm1[3]) * (1.0f / 512.0f);

    float d0 = x[0] - mu, d1 = x[1] - mu, d2 = x[2] - mu, d3 = x[3] - mu;
    float ss = d0 * d0 + d1 * d1 + d2 * d2 + d3 * d3;
#pragma unroll
    for (int o = 16; o; o >>= 1) ss += __shfl_xor_sync(0xFFFFFFFFu, ss, o);
    if (!lane) sm2[w] = ss;
    __syncthreads();
    float var = (sm2[0] + sm2[1] + sm2[2] + sm2[3]) * (1.0f / 512.0f);
    float inv = rsqrtf(var + LN_EPS);

    float4 gg = ((const float4*)g)[tid];
    float4 bv = ((const float4*)bb)[tid];
    float4 o4;
    o4.x = d0 * inv * gg.x + bv.x;
    o4.y = d1 * inv * gg.y + bv.y;
    o4.z = d2 * inv * gg.z + bv.z;
    o4.w = d3 * inv * gg.w + bv.w;
    *(float4*)(out + base) = o4;
}

// ---------------------------------------------------------------------------
// Launch
// ---------------------------------------------------------------------------
extern "C" void kernel_launch(void* const* d_in, const int* in_sizes, int n_in,
                              void* d_out, int out_size) {
    const float* x    = (const float*)d_in[0];
    const float* Wq   = (const float*)d_in[1];
    const float* bq   = (const float*)d_in[2];
    const float* Wk   = (const float*)d_in[3];
    const float* bk   = (const float*)d_in[4];
    const float* Wv   = (const float*)d_in[5];
    const float* bv   = (const float*)d_in[6];
    const float* Wo   = (const float*)d_in[7];
    const float* bo   = (const float*)d_in[8];
    const float* ln1g = (const float*)d_in[9];
    const float* ln1b = (const float*)d_in[10];
    const float* W1   = (const float*)d_in[11];
    const float* b1   = (const float*)d_in[12];
    const float* W2   = (const float*)d_in[13];
    const float* b2   = (const float*)d_in[14];
    const float* ln2g = (const float*)d_in[15];
    const float* ln2b = (const float*)d_in[16];
    float* out = (float*)d_out;

    __nv_bfloat16 *h_hi, *h_lo, *qkv_hi, *qkv_lo, *ctx_hi, *ctx_lo,
                  *t_hi, *t_lo, *mid_hi, *mid_lo,
                  *sh_hi, *sh_lo, *qs_hi, *qs_lo,
                  *wqkvT_hi, *wqkvT_lo, *woT_hi, *woT_lo,
                  *w1T_hi, *w1T_lo, *w2T_hi, *w2T_lo;
    float* bqkv;
    cudaGetSymbolAddress((void**)&h_hi, g_h_hi);     cudaGetSymbolAddress((void**)&h_lo, g_h_lo);
    cudaGetSymbolAddress((void**)&qkv_hi, g_qkv_hi); cudaGetSymbolAddress((void**)&qkv_lo, g_qkv_lo);
    cudaGetSymbolAddress((void**)&ctx_hi, g_ctx_hi); cudaGetSymbolAddress((void**)&ctx_lo, g_ctx_lo);
    cudaGetSymbolAddress((void**)&t_hi, g_t_hi);     cudaGetSymbolAddress((void**)&t_lo, g_t_lo);
    cudaGetSymbolAddress((void**)&mid_hi, g_mid_hi); cudaGetSymbolAddress((void**)&mid_lo, g_mid_lo);
    cudaGetSymbolAddress((void**)&sh_hi, g_sh_hi);   cudaGetSymbolAddress((void**)&sh_lo, g_sh_lo);
    cudaGetSymbolAddress((void**)&qs_hi, g_qs_hi);   cudaGetSymbolAddress((void**)&qs_lo, g_qs_lo);
    cudaGetSymbolAddress((void**)&wqkvT_hi, g_wqkvT_hi); cudaGetSymbolAddress((void**)&wqkvT_lo, g_wqkvT_lo);
    cudaGetSymbolAddress((void**)&woT_hi, g_woT_hi); cudaGetSymbolAddress((void**)&woT_lo, g_woT_lo);
    cudaGetSymbolAddress((void**)&w1T_hi, g_w1T_hi); cudaGetSymbolAddress((void**)&w1T_lo, g_w1T_lo);
    cudaGetSymbolAddress((void**)&w2T_hi, g_w2T_hi); cudaGetSymbolAddress((void**)&w2T_lo, g_w2T_lo);
    cudaGetSymbolAddress((void**)&bqkv, g_bqkv);

    cudaFuncSetAttribute(gemm_wmma, cudaFuncAttributeMaxDynamicSharedMemorySize, GSMEM);

    const size_t WQKV = (size_t)DQKV * DM;
    const size_t WOO  = (size_t)DM * DM;
    const size_t W1S  = (size_t)DH * DM;
    const size_t W2S  = (size_t)DM * DH;

    pos_kernel<<<(MTOK * DM) / 256, 256>>>(x, h_hi, h_lo);

    for (int l = 0; l < 2; l++) {
        const size_t oW  = (size_t)l * DM * DM;
        const size_t oV  = (size_t)l * DM;
        const size_t oW1 = (size_t)l * DM * DH;
        const size_t oW2 = (size_t)l * DH * DM;
        wprep_kernel<<<3072, 256>>>(
            Wq + oW, Wk + oW, Wv + oW, Wo + oW, W1 + oW1, W2 + oW2,
            wqkvT_hi + l * WQKV, wqkvT_lo + l * WQKV,
            woT_hi + l * WOO,    woT_lo + l * WOO,
            w1T_hi + l * W1S,    w1T_lo + l * W1S,
            w2T_hi + l * W2S,    w2T_lo + l * W2S);
        bcat_kernel<<<6, 256>>>(bq + oV, bk + oV, bv + oV, bqkv + l * DQKV);
    }

    // =========================== Layer 0 (full) ===========================
    {
        const int l = 0;
        const size_t oV  = (size_t)l * DM;
        const size_t oB1 = (size_t)l * DH;

        gemm_wmma<<<dim3(DQKV / BN, MTOK / BM), 256, GSMEM>>>(
            h_hi, h_lo, wqkvT_hi + l * WQKV, wqkvT_lo + l * WQKV,
            bqkv + l * DQKV, qkv_hi, qkv_lo, DQKV, DM, 0);
        attn_kernel<<<BATCH, 256>>>(qkv_hi, qkv_lo, ctx_hi, ctx_lo);
        gemm_wmma<<<dim3(DM / BN, MTOK / BM), 256, GSMEM>>>(
            ctx_hi, ctx_lo, woT_hi + l * WOO, woT_lo + l * WOO,
            bo + oV, t_hi, t_lo, DM, DM, 0);
        ln_kernel<<<MTOK, 128>>>(t_hi, t_lo, h_hi, h_lo, ln1g + oV, ln1b + oV);
        gemm_wmma<<<dim3(DH / BN, MTOK / BM), 256, GSMEM>>>(
            h_hi, h_lo, w1T_hi + l * W1S, w1T_lo + l * W1S,
            b1 + oB1, mid_hi, mid_lo, DH, DM, 1);
        gemm_wmma<<<dim3(DM / BN, MTOK / BM), 256, GSMEM>>>(
            mid_hi, mid_lo, w2T_hi + l * W2S, w2T_lo + l * W2S,
            b2 + oV, t_hi, t_lo, DM, DH, 0);
        ln_kernel<<<MTOK, 128>>>(t_hi, t_lo, h_hi, h_lo, ln2g + oV, ln2b + oV);
    }

    // =================== Layer 1 (selected-token compact) ===================
    {
        const int l = 1;
        const size_t oV  = (size_t)l * DM;
        const size_t oB1 = (size_t)l * DH;

        // KV projection over ALL tokens (qkvT rows 512..1535)
        gemm_wmma<<<dim3(1024 / BN, MTOK / BM), 256, GSMEM>>>(
            h_hi, h_lo,
            wqkvT_hi + l * WQKV + (size_t)512 * DM,
            wqkvT_lo + l * WQKV + (size_t)512 * DM,
            bqkv + l * DQKV + 512, qkv_hi, qkv_lo, 1024, DM, 0);

        selgather_kernel<<<(MSEL * DM) / 256, 256>>>(h_hi, h_lo, sh_hi, sh_lo);
        gemm_wmma<<<dim3(DM / BN, MSEL / BM), 256, GSMEM>>>(
            sh_hi, sh_lo, wqkvT_hi + l * WQKV, wqkvT_lo + l * WQKV,
            bqkv + l * DQKV, qs_hi, qs_lo, DM, DM, 0);

        attn_sel_kernel<<<BATCH, 256>>>(qs_hi, qs_lo, qkv_hi, qkv_lo, ctx_hi, ctx_lo);

        gemm_wmma<<<dim3(DM / BN, MSEL / BM), 256, GSMEM>>>(
            ctx_hi, ctx_lo, woT_hi + l * WOO, woT_lo + l * WOO,
            bo + oV, t_hi, t_lo, DM, DM, 0);
        ln_kernel<<<MSEL, 128>>>(t_hi, t_lo, sh_hi, sh_lo, ln1g + oV, ln1b + oV);

        gemm_wmma<<<dim3(DH / BN, MSEL / BM), 256, GSMEM>>>(
            sh_hi, sh_lo, w1T_hi + l * W1S, w1T_lo + l * W1S,
            b1 + oB1, mid_hi, mid_lo, DH, DM, 1);
        gemm_wmma<<<dim3(DM / BN, MSEL / BM), 256, GSMEM>>>(
            mid_hi, mid_lo, w2T_hi + l * W2S, w2T_lo + l * W2S,
            b2 + oV, t_hi, t_lo, DM, DH, 0);
        lnout_kernel<<<MSEL, 128>>>(t_hi, t_lo, sh_hi, sh_lo, ln2g + oV, ln2b + oV, out);
    }
}